// round 17
// baseline (speedup 1.0000x reference)
#include <cuda_runtime.h>
#include <cstdint>

#define TAGS       10
#define SEQ        512
#define BATCHN     8192
#define START_TAG  8
#define STOP_TAG   9

#define TBLK       4                        // timesteps per pipeline stage
#define NBLK       (SEQ / TBLK)             // 128 time-blocks
#define STAGES     4
#define EPW        14                       // batch elems per warp (2 lanes each)
#define TSB        (EPW * TAGS * 4)         // 560 B per warp per timestep
#define WPB        4
#define BPB        (EPW * WPB)              // 56 elems per block
#define GRID       ((BATCHN + BPB - 1) / BPB)   // 147 blocks -> full-chip spread

// Backpointers: u32 per (t,b); tag n (0..7) argmax nibble at bits 4n. 16.8 MB.
// t=0 never stored / never read (reference discards the t=0 carry).
__device__ unsigned g_bp[(size_t)SEQ * BATCHN];

__device__ __forceinline__ void cp16(uint32_t s, const void* g) {
    asm volatile("cp.async.ca.shared.global [%0], [%1], 16;\n" :: "r"(s), "l"(g));
}
__device__ __forceinline__ void cp_commit() {
    asm volatile("cp.async.commit_group;\n" ::: "memory");
}
__device__ __forceinline__ void cp_wait2() {
    asm volatile("cp.async.wait_group 2;\n" ::: "memory");
}

// tournament node, tie -> left (first index); exact compares
#define TOURN(vl, il, vr, ir, mo, io) \
    { bool _p = (vr) > (vl); mo = _p ? (vr) : (vl); io = _p ? (ir) : (il); }
// final-level node: tie -> right iff hb (restores absolute first-index order
// under the half-swap permutation); exact compares
#define TOURNF(vl, il, vr, ir, hb, mo, io)                                 \
    { bool _p = ((vr) > (vl)) || (((vr) == (vl)) && (hb));                 \
      mo = _p ? (vr) : (vl); io = _p ? (ir) : (il); }

__global__ __launch_bounds__(128, 1)
void crf_viterbi17(const float* __restrict__ feats,
                   const float* __restrict__ trans,
                   float* __restrict__ out) {
    // warp-private rings: 4 warps x 4 stages x (4 ts x 560 B) = 35840 B
    __shared__ __align__(16) char ring[WPB][STAGES][TBLK * TSB];

    const int tid  = threadIdx.x;
    const int warp = tid >> 5;
    const int lane = tid & 31;
    int e          = lane >> 1;          // local elem 0..15
    const bool live = (e < EPW);         // lanes 28-31 mirror elem 13 (no stores)
    if (!live) e = EPW - 1;
    const int h    = lane & 1;           // half-swap: lane owns abs tags 4h..4h+3
    const bool hb  = (h != 0);

    int base_b = blockIdx.x * BPB;
    if (base_b > BATCHN - BPB) base_b = BATCHN - BPB;   // tail overlap (benign)
    const int b = base_b + warp * EPW + e;

    // warp slice base: base_b*40 and warp*560 are multiples of 16 -> cp16 safe
    const char*  gbase = (const char*)feats +
                         (size_t)base_b * (TAGS * 4) + (size_t)warp * TSB;
    const size_t gstep = (size_t)BATCHN * TAGS * 4;

    uint32_t s_ring0;
    asm("{ .reg .u64 t; cvta.to.shared.u64 t, %1; cvt.u32.u64 %0, t; }"
        : "=r"(s_ring0) : "l"(&ring[warp][0][0]));

    // permuted transitions: Tm[i][p] = trans[ri][(p+4h)&7], ri = (i+4h)&7
    float Tm[8][8], Tc[8], Ts[8];
#pragma unroll
    for (int i = 0; i < 8; i++) {
        const int ri = (i + 4 * h) & 7;
#pragma unroll
        for (int p = 0; p < 8; p++)
            Tm[i][p] = __ldg(trans + ri * TAGS + ((p + 4 * h) & 7));
        Tc[i] = __ldg(trans + ri * TAGS + START_TAG);
        Ts[i] = __ldg(trans + STOP_TAG * TAGS + i);
    }

    // prologue: fill stages 0..2 (35 x 16B chunks per ts; one commit per block)
#pragma unroll
    for (int s = 0; s < STAGES - 1; s++) {
        uint32_t sb = s_ring0 + s * (TBLK * TSB);
#pragma unroll
        for (int k = 0; k < TBLK; k++) {
            const char* g = gbase + (size_t)(s * TBLK + k) * gstep;
            cp16(sb + k * TSB + lane * 16, g + lane * 16);
            if (lane < 3) cp16(sb + k * TSB + 512 + lane * 16, g + 512 + lane * 16);
        }
        cp_commit();
    }

    // feat LDS offsets: h swaps the two 16B halves -> f[] in permuted order
    const int offA = e * 40 + (h ? 16 : 0);   // perm tags 0..3
    const int offB = e * 40 + (h ? 0 : 16);   // perm tags 4..7

    unsigned short* __restrict__ bp16 = (unsigned short*)g_bp;
    const unsigned xmask = h ? 0x4444u : 0u;  // perm->abs nibble fix

    float fv[8];          // state in PERMUTED coordinates

    for (int ib = 0; ib < NBLK; ib++) {
        cp_wait2();
        __syncwarp();

        const char* sp = ring[warp][ib & (STAGES - 1)];

        // prefetch time-block ib+3 into the freed stage; always commit
        {
            const int nb = ib + STAGES - 1;
            if (nb < NBLK) {
                uint32_t sb = s_ring0 + (nb & (STAGES - 1)) * (TBLK * TSB);
#pragma unroll
                for (int k = 0; k < TBLK; k++) {
                    const char* g = gbase + (size_t)(nb * TBLK + k) * gstep;
                    cp16(sb + k * TSB + lane * 16, g + lane * 16);
                    if (lane < 3)
                        cp16(sb + k * TSB + 512 + lane * 16, g + 512 + lane * 16);
                }
            }
            cp_commit();
        }

#pragma unroll
        for (int k = 0; k < TBLK; k++) {
            const int t = ib * TBLK + k;
            const char* sk = sp + k * TSB;
            float2 a0 = *(const float2*)(sk + offA);
            float2 a1 = *(const float2*)(sk + offA + 8);
            float2 b0 = *(const float2*)(sk + offB);
            float2 b1 = *(const float2*)(sk + offB + 8);
            float f[8] = { a0.x, a0.y, a1.x, a1.y, b0.x, b0.y, b1.x, b1.y };

            if (ib == 0 && k == 0) {
                // exact peeled t=0: winner prev is START for every tag
#pragma unroll
                for (int i = 0; i < 8; i++) fv[i] = Tc[i] + f[i];
                continue;   // t=0 record never stored / never read
            }

            float nf[8];
            unsigned bits = 0u;
            // owned tags = permuted rows 0..3: full max+argmax tournaments
#pragma unroll
            for (int i = 0; i < 4; i++) {
                float v0 = fv[0] + Tm[i][0], v1 = fv[1] + Tm[i][1];
                float v2 = fv[2] + Tm[i][2], v3 = fv[3] + Tm[i][3];
                float v4 = fv[4] + Tm[i][4], v5 = fv[5] + Tm[i][5];
                float v6 = fv[6] + Tm[i][6], v7 = fv[7] + Tm[i][7];
                float a0_, a1_, a2_, a3_, c0_, c1_, mx;
                int   j0, j1, j2, j3, q0, q1, bi;
                TOURN (v0, 0, v1, 1, a0_, j0);
                TOURN (v2, 2, v3, 3, a1_, j1);
                TOURN (v4, 4, v5, 5, a2_, j2);
                TOURN (v6, 6, v7, 7, a3_, j3);
                TOURN (a0_, j0, a1_, j1, c0_, q0);
                TOURN (a2_, j2, a3_, j3, c1_, q1);
                TOURNF(c0_, q0, c1_, q1, hb, mx, bi);   // abs-order tie-break
                nf[i] = mx + f[i];
                bits |= (unsigned)bi << (4 * i);
            }
            // foreign tags = permuted rows 4..7: value-only fmax trees
#pragma unroll
            for (int i = 4; i < 8; i++) {
                float v0 = fv[0] + Tm[i][0], v1 = fv[1] + Tm[i][1];
                float v2 = fv[2] + Tm[i][2], v3 = fv[3] + Tm[i][3];
                float v4 = fv[4] + Tm[i][4], v5 = fv[5] + Tm[i][5];
                float v6 = fv[6] + Tm[i][6], v7 = fv[7] + Tm[i][7];
                float mx = fmaxf(fmaxf(fmaxf(v0, v1), fmaxf(v2, v3)),
                                 fmaxf(fmaxf(v4, v5), fmaxf(v6, v7)));
                nf[i] = mx + f[i];
            }
#pragma unroll
            for (int i = 0; i < 8; i++) fv[i] = nf[i];

            // my u16: abs nibbles of tags 4h..4h+3
            if (live)
                bp16[2 * ((size_t)t * BATCHN + b) + h] =
                    (unsigned short)(bits ^ xmask);
        }
    }

    // terminal + backtrace on live h==0 lanes (identity permutation)
    if (!hb && live) {
        float tv[8];
#pragma unroll
        for (int i = 0; i < 8; i++) tv[i] = fv[i] + Ts[i];
        float a0_, a1_, a2_, a3_, c0_, c1_, mx;
        int   j0, j1, j2, j3, q0, q1, tag;
        TOURN(tv[0], 0, tv[1], 1, a0_, j0);
        TOURN(tv[2], 2, tv[3], 3, a1_, j1);
        TOURN(tv[4], 4, tv[5], 5, a2_, j2);
        TOURN(tv[6], 6, tv[7], 7, a3_, j3);
        TOURN(a0_, j0, a1_, j1, c0_, q0);
        TOURN(a2_, j2, a3_, j3, c1_, q1);
        TOURN(c0_, q0, c1_, q1, mx, tag);

        out[b] = mx;
        float* __restrict__ path = out + BATCHN;
        const unsigned* __restrict__ rec = g_bp + b;
#pragma unroll 16
        for (int t = SEQ - 1; t >= 1; t--) {
            path[(size_t)t * BATCHN + b] = (float)tag;
            const unsigned w = rec[(size_t)t * BATCHN];
            tag = (int)((w >> (4 * tag)) & 0xFu);
        }
        path[b] = (float)tag;
    }
}

extern "C" void kernel_launch(void* const* d_in, const int* in_sizes, int n_in,
                              void* d_out, int out_size) {
    const float* feats = (const float*)d_in[0];
    const float* trans = (const float*)d_in[1];
    float* out = (float*)d_out;

    // 147 blocks x 128 threads: full-chip spread, scalar ops (R13 core)
    crf_viterbi17<<<GRID, 128>>>(feats, trans, out);
}